// round 1
// baseline (speedup 1.0000x reference)
#include <cuda_runtime.h>
#include <cstdint>

// Problem constants
#define CND   256                 // feature channels
#define VN    4096                // codebook size
#define NPTS  32768               // total points = 8 * 16^3
#define PB    4096                // points per batch (16^3)
#define A_ELEMS (NPTS * CND)      // 8,388,608 elements per quant output

// GEMM tiling
#define TM 128                    // points per block
#define TV 128                    // codewords per tile
#define KC 16                     // K-chunk
#define NKC (CND / KC)            // 16
#define NVT (VN / TV)             // 32
#define SX_STRIDE 132             // padded smem row stride (floats)
#define SW_STRIDE 132

#define NBLOCKS_VQ (NPTS / TM)    // 256
#define NBLOCKS_WR 128            // writer blocks (256 threads each)

// Scratch (device globals; no allocation allowed)
__device__ float  g_wsq[VN];
__device__ int    g_idx[NPTS];
__device__ double g_blocksum[NBLOCKS_WR];

// ---------------------------------------------------------------------------
// Kernel 0: per-codeword squared norms ||w_v||^2
// ---------------------------------------------------------------------------
__global__ void wsq_kernel(const float* __restrict__ W) {
    int v = blockIdx.x * blockDim.x + threadIdx.x;
    if (v < VN) {
        const float* row = W + (size_t)v * CND;
        float s = 0.f;
        #pragma unroll 8
        for (int c = 0; c < CND; c++) s = fmaf(row[c], row[c], s);
        g_wsq[v] = s;
    }
}

// ---------------------------------------------------------------------------
// Kernel 1: fused distance-GEMM + argmin.
// Each block: TM=128 points, loops over all V in TV=128 tiles.
// score(v) = ||w_v||^2 - 2 * x.w_v   (||x||^2 constant per point -> argmin-safe)
// ---------------------------------------------------------------------------
struct WPF { float4 a, b; };

__device__ __forceinline__ WPF load_w_chunk(const float* __restrict__ W,
                                            int v0, int k0, int tid) {
    WPF r;
    int i0 = tid, i1 = tid + 256;
    r.a = *reinterpret_cast<const float4*>(
        W + (size_t)(v0 + (i0 >> 2)) * CND + k0 + ((i0 & 3) << 2));
    r.b = *reinterpret_cast<const float4*>(
        W + (size_t)(v0 + (i1 >> 2)) * CND + k0 + ((i1 & 3) << 2));
    return r;
}

__device__ __forceinline__ void store_w_chunk(float* __restrict__ swb,
                                              const WPF& pf, int tid) {
    // transpose [v][k0..k0+15] -> sw[k][v]  (K-major for the GEMM microkernel)
    {
        int i0 = tid;
        int v = i0 >> 2, j = i0 & 3;
        float* d = swb + (4 * j) * SW_STRIDE + v;
        d[0]             = pf.a.x;
        d[SW_STRIDE]     = pf.a.y;
        d[2 * SW_STRIDE] = pf.a.z;
        d[3 * SW_STRIDE] = pf.a.w;
    }
    {
        int i1 = tid + 256;
        int v = i1 >> 2, j = i1 & 3;
        float* d = swb + (4 * j) * SW_STRIDE + v;
        d[0]             = pf.b.x;
        d[SW_STRIDE]     = pf.b.y;
        d[2 * SW_STRIDE] = pf.b.z;
        d[3 * SW_STRIDE] = pf.b.w;
    }
}

__global__ __launch_bounds__(256, 1)
void vq_kernel(const float* __restrict__ G, const float* __restrict__ W,
               float* __restrict__ out_idx) {
    extern __shared__ float smem[];
    float* sx   = smem;                        // [CND][SX_STRIDE]  (x tile, K-major)
    float* sw   = smem + CND * SX_STRIDE;      // 2 x [KC][SW_STRIDE] (W tile dbuf)
    float* swsq = sw + 2 * KC * SW_STRIDE;     // [TV]

    const int tid = threadIdx.x;
    const int tx  = tid & 15;                  // m-direction (points)
    const int ty  = tid >> 4;                  // v-direction (codewords)
    const int n0  = blockIdx.x * TM;
    const int b   = n0 / PB;
    const int p0  = n0 % PB;
    const float* Gb = G + (size_t)b * CND * PB + p0;

    // Stage the full x tile once: 256 rows x 128 contiguous floats (coalesced).
    for (int i = tid; i < CND * (TM / 4); i += 256) {
        int c  = i >> 5;                       // TM/4 == 32
        int m4 = i & 31;
        float4 v = *reinterpret_cast<const float4*>(Gb + (size_t)c * PB + m4 * 4);
        *reinterpret_cast<float4*>(sx + c * SX_STRIDE + m4 * 4) = v;
    }

    float best[8];
    int   bidx[8];
    #pragma unroll
    for (int i = 0; i < 8; i++) { best[i] = 3.4e38f; bidx[i] = 0; }

    __syncthreads();

    #pragma unroll 1
    for (int vt = 0; vt < NVT; vt++) {
        const int v0 = vt * TV;

        float acc[8][8];
        #pragma unroll
        for (int i = 0; i < 8; i++)
            #pragma unroll
            for (int j = 0; j < 8; j++) acc[i][j] = 0.f;

        if (tid < TV) swsq[tid] = g_wsq[v0 + tid];

        WPF pf = load_w_chunk(W, v0, 0, tid);
        store_w_chunk(sw, pf, tid);
        __syncthreads();

        int cur = 0;
        #pragma unroll 1
        for (int kc = 0; kc < NKC; kc++) {
            const bool has_next = (kc + 1 < NKC);
            if (has_next) pf = load_w_chunk(W, v0, (kc + 1) * KC, tid);

            const float* sxr0 = sx + kc * KC * SX_STRIDE + tx * 8;
            const float* swr0 = sw + cur * KC * SW_STRIDE + ty * 8;
            #pragma unroll
            for (int k = 0; k < KC; k++) {
                float a[8], bb[8];
                *reinterpret_cast<float4*>(&a[0]) =
                    *reinterpret_cast<const float4*>(sxr0 + k * SX_STRIDE);
                *reinterpret_cast<float4*>(&a[4]) =
                    *reinterpret_cast<const float4*>(sxr0 + k * SX_STRIDE + 4);
                *reinterpret_cast<float4*>(&bb[0]) =
                    *reinterpret_cast<const float4*>(swr0 + k * SW_STRIDE);
                *reinterpret_cast<float4*>(&bb[4]) =
                    *reinterpret_cast<const float4*>(swr0 + k * SW_STRIDE + 4);
                #pragma unroll
                for (int i = 0; i < 8; i++)
                    #pragma unroll
                    for (int j = 0; j < 8; j++)
                        acc[i][j] = fmaf(a[i], bb[j], acc[i][j]);
            }
            __syncthreads();
            if (has_next) {
                store_w_chunk(sw + (cur ^ 1) * KC * SW_STRIDE, pf, tid);
                cur ^= 1;
                __syncthreads();
            }
        }

        // Epilogue: score + running argmin. Strict '<' + ascending v order
        // ensures ties resolve to the smallest index (matches jnp.argmin).
        #pragma unroll
        for (int j = 0; j < 8; j++) {
            const int   vv = v0 + ty * 8 + j;
            const float ws = swsq[ty * 8 + j];
            #pragma unroll
            for (int i = 0; i < 8; i++) {
                float s = fmaf(-2.f, acc[i][j], ws);
                if (s < best[i]) { best[i] = s; bidx[i] = vv; }
            }
        }
        __syncthreads();   // protect swsq/sw before next tile rewrites them
    }

    // Cross-thread reduction: 16 ty-partials per point, in reused sw smem.
    float* rs = sw;                       // [16][TM] scores
    int*   ri = (int*)(sw + 16 * TM);     // [16][TM] indices
    #pragma unroll
    for (int i = 0; i < 8; i++) {
        rs[ty * TM + tx * 8 + i] = best[i];
        ri[ty * TM + tx * 8 + i] = bidx[i];
    }
    __syncthreads();
    if (tid < TM) {
        float bs = rs[tid];
        int   bi = ri[tid];
        #pragma unroll 1
        for (int t = 1; t < 16; t++) {
            float s  = rs[t * TM + tid];
            int   ii = ri[t * TM + tid];
            if (s < bs || (s == bs && ii < bi)) { bs = s; bi = ii; }
        }
        const int n = n0 + tid;
        g_idx[n]   = bi;
        out_idx[n] = (float)bi;
    }
}

// ---------------------------------------------------------------------------
// Kernel 2: scatter quant_feat / quant_feat_st + per-block fp64 MSE partials.
// Thread n handles one point across all 256 channels (writes coalesced over p).
// ---------------------------------------------------------------------------
__global__ __launch_bounds__(256)
void write_kernel(const float* __restrict__ G, const float* __restrict__ W,
                  float* __restrict__ out) {
    const int n = blockIdx.x * blockDim.x + threadIdx.x;
    const int b = n / PB;
    const int p = n % PB;
    const int idx = g_idx[n];
    const float* wrow = W + (size_t)idx * CND;
    const float* g    = G + (size_t)b * CND * PB + p;
    float* q1 = out + (size_t)b * CND * PB + p;
    float* q2 = q1 + (size_t)A_ELEMS;

    double sum = 0.0;
    #pragma unroll 4
    for (int c = 0; c < CND; c++) {
        float w  = __ldg(wrow + c);
        float gg = g[(size_t)c * PB];
        q1[(size_t)c * PB] = w;
        q2[(size_t)c * PB] = w;
        float d = gg - w;
        sum += (double)d * (double)d;
    }

    __shared__ double sred[256];
    sred[threadIdx.x] = sum;
    __syncthreads();
    for (int s = 128; s > 0; s >>= 1) {
        if (threadIdx.x < s) sred[threadIdx.x] += sred[threadIdx.x + s];
        __syncthreads();
    }
    if (threadIdx.x == 0) g_blocksum[blockIdx.x] = sred[0];
}

// ---------------------------------------------------------------------------
// Kernel 3: deterministic final sum -> quant_diff scalar
// ---------------------------------------------------------------------------
__global__ void final_kernel(float* __restrict__ out) {
    double s = 0.0;
    for (int i = 0; i < NBLOCKS_WR; i++) s += g_blocksum[i];
    out[2 * (size_t)A_ELEMS + NPTS] = (float)(s / ((double)NPTS * (double)CND));
}

// ---------------------------------------------------------------------------
// Launch. Output layout (float32, concatenated in reference return order):
//   [0, A)           quant_feat       (b, c, x, y, z)
//   [A, 2A)          quant_feat_st    (numerically identical to quant_feat)
//   [2A, 2A+NPTS)    enc_idx          (cast to float)
//   [2A+NPTS]        quant_diff
// ---------------------------------------------------------------------------
extern "C" void kernel_launch(void* const* d_in, const int* in_sizes, int n_in,
                              void* d_out, int out_size) {
    const float* G = (const float*)d_in[0];   // grid_feat [8,256,16,16,16]
    const float* W = (const float*)d_in[1];   // weight    [4096,256]
    float* out = (float*)d_out;

    const int smem_bytes = (CND * SX_STRIDE + 2 * KC * SW_STRIDE + TV) * 4;
    cudaFuncSetAttribute(vq_kernel, cudaFuncAttributeMaxDynamicSharedMemorySize,
                         smem_bytes);

    wsq_kernel<<<(VN + 255) / 256, 256>>>(W);
    vq_kernel<<<NBLOCKS_VQ, 256, smem_bytes>>>(G, W, out + 2 * (size_t)A_ELEMS);
    write_kernel<<<NBLOCKS_WR, 256>>>(G, W, out);
    final_kernel<<<1, 1>>>(out);
}